// round 15
// baseline (speedup 1.0000x reference)
#include <cuda_runtime.h>
#include <cuda_fp16.h>

// VoxelMorph SpatialTransformer, trilinear, zero padding.
// Smem-tiled gather v9: fp16x2 corner tile 20x16x32 (99.4KB, 2x1024-thread
// CTAs/SM, amp 2.43x) + packed fma.rn.f32x2 dual-channel accumulation.
// Weights/accumulation fp32; boundary fallback exact fp32.
// src:  [B=2, C=2, 160, 192, 160] f32
// flow: [B=2, 3,   160, 192, 160] f32  (dz, dy, dx)
// out:  [B=2, C=2, 160, 192, 160] f32

namespace {
constexpr int D = 160, H = 192, W = 160, C = 2, B = 2;
constexpr int N  = D * H * W;
constexpr int HW = H * W;

constexpr int TZ = 20, TY = 16, TX = 32;  // output tile (10240 voxels)
constexpr int R  = 3;
constexpr int SZ = TZ + 1 + 2 * R;        // 27 z-slices
constexpr int SY = TY + 1 + 2 * R;        // 23 y-rows
constexpr int SXP = 40;                   // x entries (half2), quad-aligned
constexpr int ROWS = SZ * SY;             // 621
constexpr int QPR  = SXP / 4;             // 10 quads per row
constexpr int SMEM_BYTES = ROWS * SXP * 4;    // 99360
constexpr int NZT = D / TZ;               // 8
constexpr int ZPT = 10;                   // z-planes per thread (2 z groups)
constexpr int NTHREADS = 1024;
// smem x coordinate: x' = gx - (x_t - 4); valid gather x' in [1, 38]
}

__device__ __forceinline__ unsigned h2_bits(__half2 h) {
    return *reinterpret_cast<unsigned*>(&h);
}
__device__ __forceinline__ unsigned long long pk2(float lo, float hi) {
    unsigned long long r;
    asm("mov.b64 %0, {%1, %2};" : "=l"(r) : "f"(lo), "f"(hi));
    return r;
}
__device__ __forceinline__ unsigned long long pkc(float2 c) {
    return pk2(c.x, c.y);
}
__device__ __forceinline__ unsigned long long mul2(unsigned long long a,
                                                   unsigned long long b) {
    unsigned long long d;
    asm("mul.rn.f32x2 %0, %1, %2;" : "=l"(d) : "l"(a), "l"(b));
    return d;
}
__device__ __forceinline__ unsigned long long fma2(unsigned long long a,
                                                   unsigned long long b,
                                                   unsigned long long c) {
    unsigned long long d;
    asm("fma.rn.f32x2 %0, %1, %2, %3;" : "=l"(d) : "l"(a), "l"(b), "l"(c));
    return d;
}

__global__ __launch_bounds__(NTHREADS, 2)
void st_v13_kernel(const float* __restrict__ src,
                   const float* __restrict__ flow,
                   float* __restrict__ out)
{
    extern __shared__ __half2 smh[];      // [SZ*SY][SXP], (ch0, ch1)

    const int bzz = blockIdx.z;
    const int b   = bzz / NZT;
    const int z_t = (bzz - b * NZT) * TZ;
    const int y_t = blockIdx.y * TY;
    const int x_t = blockIdx.x * TX;
    const int z_lo = z_t - R, y_lo = y_t - R;
    const int x_al = x_t - 4;             // smem x' = gx - x_al

    const int tid = (threadIdx.z * TY + threadIdx.y) * TX + threadIdx.x;

    const float* s0 = src + b * C * N;
    const float* s1 = s0 + N;

    // ---- fill: (row, quad) units; 2x LDG.128 -> 4x half2 -> 1x STS.128 ----
    for (int u = tid; u < ROWS * QPR; u += NTHREADS) {
        const int row = u / QPR;
        const int qi  = u - row * QPR;
        const int sz  = row / SY;
        const int sy  = row - sz * SY;
        const int gz  = z_lo + sz;
        const int gy  = y_lo + sy;
        const int gx  = x_al + 4 * qi;    // multiple of 4
        float4 q0 = make_float4(0.f, 0.f, 0.f, 0.f);
        float4 q1 = q0;
        if (((unsigned)gz < (unsigned)D) & ((unsigned)gy < (unsigned)H) &
            ((unsigned)gx < (unsigned)W)) {
            const int off = (gz * H + gy) * W + gx;   // 16B-aligned
            q0 = __ldg((const float4*)(s0 + off));
            q1 = __ldg((const float4*)(s1 + off));
        }
        const __half2 h0 = __floats2half2_rn(q0.x, q1.x);
        const __half2 h1 = __floats2half2_rn(q0.y, q1.y);
        const __half2 h2 = __floats2half2_rn(q0.z, q1.z);
        const __half2 h3 = __floats2half2_rn(q0.w, q1.w);
        const uint4 packed = make_uint4(h2_bits(h0), h2_bits(h1),
                                        h2_bits(h2), h2_bits(h3));
        *((uint4*)(smh + row * SXP + 4 * qi)) = packed;     // 16B-aligned
    }
    __syncthreads();

    // ---- gather: each thread handles ZPT z-planes ----
    const int h = y_t + threadIdx.y;
    const int w = x_t + threadIdx.x;
    const int z_b = z_t + threadIdx.z * ZPT;

    const float* fb = flow + b * 3 * N;
    float* ob = out + b * C * N;

    int s = (z_b * H + h) * W + w;

    #pragma unroll 5
    for (int k = 0; k < ZPT; ++k, s += HW) {
        const int d = z_b + k;

        const float zf = (float)d + __ldcs(fb + s);
        const float yf = (float)h + __ldcs(fb + s + N);
        const float xf = (float)w + __ldcs(fb + s + 2 * N);

        const int z0 = __float2int_rd(zf);
        const int y0 = __float2int_rd(yf);
        const int x0 = __float2int_rd(xf);
        const float fz = zf - (float)z0;
        const float fy = yf - (float)y0;
        const float fx = xf - (float)x0;
        const float gz = 1.0f - fz, gy = 1.0f - fy, gx = 1.0f - fx;

        const float w00 = gz * gy, w01 = gz * fy, w10 = fz * gy, w11 = fz * fy;
        const float w000 = w00 * gx, w001 = w00 * fx;
        const float w010 = w01 * gx, w011 = w01 * fx;
        const float w100 = w10 * gx, w101 = w10 * fx;
        const float w110 = w11 * gx, w111 = w11 * fx;

        const int z0l = z0 - z_lo;        // in-tile: [0, SZ-2]
        const int y0l = y0 - y_lo;        // in-tile: [0, SY-2]
        const int x0l = x0 - x_al;        // in-tile: [1, SXP-2]

        float a0, a1;

        if (((unsigned)z0l <= (unsigned)(SZ - 2)) &
            ((unsigned)y0l <= (unsigned)(SY - 2)) &
            ((unsigned)(x0l - 1) <= (unsigned)(SXP - 3))) {
            const __half2* p = smh + (z0l * SY + y0l) * SXP + x0l;
            const float2 c000 = __half22float2(p[0]);
            const float2 c001 = __half22float2(p[1]);
            const float2 c010 = __half22float2(p[SXP]);
            const float2 c011 = __half22float2(p[SXP + 1]);
            const float2 c100 = __half22float2(p[SY * SXP]);
            const float2 c101 = __half22float2(p[SY * SXP + 1]);
            const float2 c110 = __half22float2(p[SY * SXP + SXP]);
            const float2 c111 = __half22float2(p[SY * SXP + SXP + 1]);

            unsigned long long acc = mul2(pk2(w000, w000), pkc(c000));
            acc = fma2(pk2(w001, w001), pkc(c001), acc);
            acc = fma2(pk2(w010, w010), pkc(c010), acc);
            acc = fma2(pk2(w011, w011), pkc(c011), acc);
            acc = fma2(pk2(w100, w100), pkc(c100), acc);
            acc = fma2(pk2(w101, w101), pkc(c101), acc);
            acc = fma2(pk2(w110, w110), pkc(c110), acc);
            acc = fma2(pk2(w111, w111), pkc(c111), acc);
            asm("mov.b64 {%0, %1}, %2;" : "=f"(a0), "=f"(a1) : "l"(acc));
        } else {
            // rare fallback: sample escapes tile (|flow| > R) — exact fp32
            a0 = 0.0f; a1 = 0.0f;
            #pragma unroll
            for (int dz = 0; dz < 2; ++dz) {
                const int zi = z0 + dz;
                if ((unsigned)zi >= (unsigned)D) continue;
                const float wz = dz ? fz : gz;
                #pragma unroll
                for (int dy = 0; dy < 2; ++dy) {
                    const int yi = y0 + dy;
                    if ((unsigned)yi >= (unsigned)H) continue;
                    const float wzy = wz * (dy ? fy : gy);
                    #pragma unroll
                    for (int dx = 0; dx < 2; ++dx) {
                        const int xi = x0 + dx;
                        if ((unsigned)xi >= (unsigned)W) continue;
                        const float wgt = wzy * (dx ? fx : gx);
                        const int lin = (zi * H + yi) * W + xi;
                        a0 += wgt * __ldg(s0 + lin);
                        a1 += wgt * __ldg(s1 + lin);
                    }
                }
            }
        }

        __stcs(ob + s,     a0);
        __stcs(ob + s + N, a1);
    }
}

extern "C" void kernel_launch(void* const* d_in, const int* in_sizes, int n_in,
                              void* d_out, int out_size)
{
    const float* src  = (const float*)d_in[0];
    const float* flow = (const float*)d_in[1];
    float* out = (float*)d_out;

    static bool attr_done = false;
    if (!attr_done) {
        cudaFuncSetAttribute(st_v13_kernel,
                             cudaFuncAttributeMaxDynamicSharedMemorySize,
                             SMEM_BYTES);
        attr_done = true;
    }

    dim3 block(TX, TY, 2);                  // 1024 threads
    dim3 grid(W / TX, H / TY, B * NZT);     // 5, 12, 16
    st_v13_kernel<<<grid, block, SMEM_BYTES>>>(src, flow, out);
}

// round 16
// speedup vs baseline: 1.0236x; 1.0236x over previous
#include <cuda_runtime.h>
#include <cuda_fp16.h>

// VoxelMorph SpatialTransformer, trilinear, zero padding.
// Smem-tiled gather v10: R14's scalar-FFMA gather (79.7us winner) with only
// the tile enlarged to 20x16x32 (99.4KB, 2x1024-thread CTAs/SM, amp 2.43x).
// fp16x2 (ch0,ch1) corner tile; weights/accumulation fp32; boundary fallback
// exact fp32.
// src:  [B=2, C=2, 160, 192, 160] f32
// flow: [B=2, 3,   160, 192, 160] f32  (dz, dy, dx)
// out:  [B=2, C=2, 160, 192, 160] f32

namespace {
constexpr int D = 160, H = 192, W = 160, C = 2, B = 2;
constexpr int N  = D * H * W;
constexpr int HW = H * W;

constexpr int TZ = 20, TY = 16, TX = 32;  // output tile (10240 voxels)
constexpr int R  = 3;
constexpr int SZ = TZ + 1 + 2 * R;        // 27 z-slices
constexpr int SY = TY + 1 + 2 * R;        // 23 y-rows
constexpr int SXP = 40;                   // x entries (half2), quad-aligned
constexpr int ROWS = SZ * SY;             // 621
constexpr int QPR  = SXP / 4;             // 10 quads per row
constexpr int SMEM_BYTES = ROWS * SXP * 4;    // 99360
constexpr int NZT = D / TZ;               // 8
constexpr int ZPT = 10;                   // z-planes per thread (2 z groups)
constexpr int NTHREADS = 1024;
// smem x coordinate: x' = gx - (x_t - 4); valid gather x' in [1, 38]
}

__device__ __forceinline__ unsigned h2_bits(__half2 h) {
    return *reinterpret_cast<unsigned*>(&h);
}

__global__ __launch_bounds__(NTHREADS, 2)
void st_v14_kernel(const float* __restrict__ src,
                   const float* __restrict__ flow,
                   float* __restrict__ out)
{
    extern __shared__ __half2 smh[];      // [SZ*SY][SXP], (ch0, ch1)

    const int bzz = blockIdx.z;
    const int b   = bzz / NZT;
    const int z_t = (bzz - b * NZT) * TZ;
    const int y_t = blockIdx.y * TY;
    const int x_t = blockIdx.x * TX;
    const int z_lo = z_t - R, y_lo = y_t - R;
    const int x_al = x_t - 4;             // smem x' = gx - x_al

    const int tid = (threadIdx.z * TY + threadIdx.y) * TX + threadIdx.x;

    const float* s0 = src + b * C * N;
    const float* s1 = s0 + N;

    // ---- fill: (row, quad) units; 2x LDG.128 -> 4x half2 -> 1x STS.128 ----
    for (int u = tid; u < ROWS * QPR; u += NTHREADS) {
        const int row = u / QPR;
        const int qi  = u - row * QPR;
        const int sz  = row / SY;
        const int sy  = row - sz * SY;
        const int gz  = z_lo + sz;
        const int gy  = y_lo + sy;
        const int gx  = x_al + 4 * qi;    // multiple of 4
        float4 q0 = make_float4(0.f, 0.f, 0.f, 0.f);
        float4 q1 = q0;
        if (((unsigned)gz < (unsigned)D) & ((unsigned)gy < (unsigned)H) &
            ((unsigned)gx < (unsigned)W)) {
            const int off = (gz * H + gy) * W + gx;   // 16B-aligned
            q0 = __ldg((const float4*)(s0 + off));
            q1 = __ldg((const float4*)(s1 + off));
        }
        const __half2 h0 = __floats2half2_rn(q0.x, q1.x);
        const __half2 h1 = __floats2half2_rn(q0.y, q1.y);
        const __half2 h2 = __floats2half2_rn(q0.z, q1.z);
        const __half2 h3 = __floats2half2_rn(q0.w, q1.w);
        const uint4 packed = make_uint4(h2_bits(h0), h2_bits(h1),
                                        h2_bits(h2), h2_bits(h3));
        *((uint4*)(smh + row * SXP + 4 * qi)) = packed;     // 16B-aligned
    }
    __syncthreads();

    // ---- gather: each thread handles ZPT z-planes ----
    const int h = y_t + threadIdx.y;
    const int w = x_t + threadIdx.x;
    const int z_b = z_t + threadIdx.z * ZPT;

    const float* fb = flow + b * 3 * N;
    float* ob = out + b * C * N;

    int s = (z_b * H + h) * W + w;

    #pragma unroll 5
    for (int k = 0; k < ZPT; ++k, s += HW) {
        const int d = z_b + k;

        const float zf = (float)d + __ldcs(fb + s);
        const float yf = (float)h + __ldcs(fb + s + N);
        const float xf = (float)w + __ldcs(fb + s + 2 * N);

        const int z0 = __float2int_rd(zf);
        const int y0 = __float2int_rd(yf);
        const int x0 = __float2int_rd(xf);
        const float fz = zf - (float)z0;
        const float fy = yf - (float)y0;
        const float fx = xf - (float)x0;
        const float gz = 1.0f - fz, gy = 1.0f - fy, gx = 1.0f - fx;

        const float w00 = gz * gy, w01 = gz * fy, w10 = fz * gy, w11 = fz * fy;
        const float w000 = w00 * gx, w001 = w00 * fx;
        const float w010 = w01 * gx, w011 = w01 * fx;
        const float w100 = w10 * gx, w101 = w10 * fx;
        const float w110 = w11 * gx, w111 = w11 * fx;

        const int z0l = z0 - z_lo;        // in-tile: [0, SZ-2]
        const int y0l = y0 - y_lo;        // in-tile: [0, SY-2]
        const int x0l = x0 - x_al;        // in-tile: [1, SXP-2]

        float a0, a1;

        if (((unsigned)z0l <= (unsigned)(SZ - 2)) &
            ((unsigned)y0l <= (unsigned)(SY - 2)) &
            ((unsigned)(x0l - 1) <= (unsigned)(SXP - 3))) {
            const __half2* p = smh + (z0l * SY + y0l) * SXP + x0l;
            const float2 c000 = __half22float2(p[0]);
            const float2 c001 = __half22float2(p[1]);
            const float2 c010 = __half22float2(p[SXP]);
            const float2 c011 = __half22float2(p[SXP + 1]);
            const float2 c100 = __half22float2(p[SY * SXP]);
            const float2 c101 = __half22float2(p[SY * SXP + 1]);
            const float2 c110 = __half22float2(p[SY * SXP + SXP]);
            const float2 c111 = __half22float2(p[SY * SXP + SXP + 1]);
            a0 = w000 * c000.x + w001 * c001.x
               + w010 * c010.x + w011 * c011.x
               + w100 * c100.x + w101 * c101.x
               + w110 * c110.x + w111 * c111.x;
            a1 = w000 * c000.y + w001 * c001.y
               + w010 * c010.y + w011 * c011.y
               + w100 * c100.y + w101 * c101.y
               + w110 * c110.y + w111 * c111.y;
        } else {
            // rare fallback: sample escapes tile (|flow| > R) — exact fp32
            a0 = 0.0f; a1 = 0.0f;
            #pragma unroll
            for (int dz = 0; dz < 2; ++dz) {
                const int zi = z0 + dz;
                if ((unsigned)zi >= (unsigned)D) continue;
                const float wz = dz ? fz : gz;
                #pragma unroll
                for (int dy = 0; dy < 2; ++dy) {
                    const int yi = y0 + dy;
                    if ((unsigned)yi >= (unsigned)H) continue;
                    const float wzy = wz * (dy ? fy : gy);
                    #pragma unroll
                    for (int dx = 0; dx < 2; ++dx) {
                        const int xi = x0 + dx;
                        if ((unsigned)xi >= (unsigned)W) continue;
                        const float wgt = wzy * (dx ? fx : gx);
                        const int lin = (zi * H + yi) * W + xi;
                        a0 += wgt * __ldg(s0 + lin);
                        a1 += wgt * __ldg(s1 + lin);
                    }
                }
            }
        }

        __stcs(ob + s,     a0);
        __stcs(ob + s + N, a1);
    }
}

extern "C" void kernel_launch(void* const* d_in, const int* in_sizes, int n_in,
                              void* d_out, int out_size)
{
    const float* src  = (const float*)d_in[0];
    const float* flow = (const float*)d_in[1];
    float* out = (float*)d_out;

    static bool attr_done = false;
    if (!attr_done) {
        cudaFuncSetAttribute(st_v14_kernel,
                             cudaFuncAttributeMaxDynamicSharedMemorySize,
                             SMEM_BYTES);
        attr_done = true;
    }

    dim3 block(TX, TY, 2);                  // 1024 threads
    dim3 grid(W / TX, H / TY, B * NZT);     // 5, 12, 16
    st_v14_kernel<<<grid, block, SMEM_BYTES>>>(src, flow, out);
}

// round 17
// speedup vs baseline: 1.3089x; 1.2787x over previous
#include <cuda_runtime.h>
#include <cuda_fp16.h>

// VoxelMorph SpatialTransformer, trilinear, zero padding.
// Smem-tiled gather v11: R14's winning geometry (16x16x32 tile, 84.6KB,
// 2x1024-thread CTAs/SM) with half2-packed x-lerp (HSUB2+HFMA2) replacing
// 8 corner converts + x FFMAs. y/z lerp + weights stay fp32; boundary
// fallback exact fp32.
// src:  [B=2, C=2, 160, 192, 160] f32
// flow: [B=2, 3,   160, 192, 160] f32  (dz, dy, dx)
// out:  [B=2, C=2, 160, 192, 160] f32

namespace {
constexpr int D = 160, H = 192, W = 160, C = 2, B = 2;
constexpr int N  = D * H * W;
constexpr int HW = H * W;

constexpr int TZ = 16, TY = 16, TX = 32;  // output tile (8192 voxels)
constexpr int R  = 3;
constexpr int SZ = TZ + 1 + 2 * R;        // 23 z-slices
constexpr int SY = TY + 1 + 2 * R;        // 23 y-rows
constexpr int SXP = 40;                   // x entries (half2), quad-aligned
constexpr int ROWS = SZ * SY;             // 529
constexpr int QPR  = SXP / 4;             // 10 quads per row
constexpr int SMEM_BYTES = ROWS * SXP * 4;    // 84640
constexpr int NZT = D / TZ;               // 10
constexpr int ZPT = 8;                    // z-planes per thread (2 z groups)
constexpr int NTHREADS = 1024;
// smem x coordinate: x' = gx - (x_t - 4); valid gather x' in [1, 38]
}

__device__ __forceinline__ unsigned h2_bits(__half2 h) {
    return *reinterpret_cast<unsigned*>(&h);
}

__global__ __launch_bounds__(NTHREADS, 2)
void st_v15_kernel(const float* __restrict__ src,
                   const float* __restrict__ flow,
                   float* __restrict__ out)
{
    extern __shared__ __half2 smh[];      // [SZ*SY][SXP], (ch0, ch1)

    const int bzz = blockIdx.z;
    const int b   = bzz / NZT;
    const int z_t = (bzz - b * NZT) * TZ;
    const int y_t = blockIdx.y * TY;
    const int x_t = blockIdx.x * TX;
    const int z_lo = z_t - R, y_lo = y_t - R;
    const int x_al = x_t - 4;             // smem x' = gx - x_al

    const int tid = (threadIdx.z * TY + threadIdx.y) * TX + threadIdx.x;

    const float* s0 = src + b * C * N;
    const float* s1 = s0 + N;

    // ---- fill: (row, quad) units; 2x LDG.128 -> 4x half2 -> 1x STS.128 ----
    for (int u = tid; u < ROWS * QPR; u += NTHREADS) {
        const int row = u / QPR;
        const int qi  = u - row * QPR;
        const int sz  = row / SY;
        const int sy  = row - sz * SY;
        const int gz  = z_lo + sz;
        const int gy  = y_lo + sy;
        const int gx  = x_al + 4 * qi;    // multiple of 4
        float4 q0 = make_float4(0.f, 0.f, 0.f, 0.f);
        float4 q1 = q0;
        if (((unsigned)gz < (unsigned)D) & ((unsigned)gy < (unsigned)H) &
            ((unsigned)gx < (unsigned)W)) {
            const int off = (gz * H + gy) * W + gx;   // 16B-aligned
            q0 = __ldg((const float4*)(s0 + off));
            q1 = __ldg((const float4*)(s1 + off));
        }
        const __half2 h0 = __floats2half2_rn(q0.x, q1.x);
        const __half2 h1 = __floats2half2_rn(q0.y, q1.y);
        const __half2 h2 = __floats2half2_rn(q0.z, q1.z);
        const __half2 h3 = __floats2half2_rn(q0.w, q1.w);
        const uint4 packed = make_uint4(h2_bits(h0), h2_bits(h1),
                                        h2_bits(h2), h2_bits(h3));
        *((uint4*)(smh + row * SXP + 4 * qi)) = packed;     // 16B-aligned
    }
    __syncthreads();

    // ---- gather: each thread handles ZPT z-planes ----
    const int h = y_t + threadIdx.y;
    const int w = x_t + threadIdx.x;
    const int z_b = z_t + threadIdx.z * ZPT;

    const float* fb = flow + b * 3 * N;
    float* ob = out + b * C * N;

    int s = (z_b * H + h) * W + w;

    #pragma unroll 4
    for (int k = 0; k < ZPT; ++k, s += HW) {
        const int d = z_b + k;

        const float zf = (float)d + __ldcs(fb + s);
        const float yf = (float)h + __ldcs(fb + s + N);
        const float xf = (float)w + __ldcs(fb + s + 2 * N);

        const int z0 = __float2int_rd(zf);
        const int y0 = __float2int_rd(yf);
        const int x0 = __float2int_rd(xf);
        const float fz = zf - (float)z0;
        const float fy = yf - (float)y0;
        const float fx = xf - (float)x0;
        const float gz = 1.0f - fz, gy = 1.0f - fy;

        const float w00 = gz * gy, w01 = gz * fy, w10 = fz * gy, w11 = fz * fy;

        const int z0l = z0 - z_lo;        // in-tile: [0, SZ-2]
        const int y0l = y0 - y_lo;        // in-tile: [0, SY-2]
        const int x0l = x0 - x_al;        // in-tile: [1, SXP-2]

        float a0, a1;

        if (((unsigned)z0l <= (unsigned)(SZ - 2)) &
            ((unsigned)y0l <= (unsigned)(SY - 2)) &
            ((unsigned)(x0l - 1) <= (unsigned)(SXP - 3))) {
            const __half2* p = smh + (z0l * SY + y0l) * SXP + x0l;
            const __half2 c000 = p[0];
            const __half2 c001 = p[1];
            const __half2 c010 = p[SXP];
            const __half2 c011 = p[SXP + 1];
            const __half2 c100 = p[SY * SXP];
            const __half2 c101 = p[SY * SXP + 1];
            const __half2 c110 = p[SY * SXP + SXP];
            const __half2 c111 = p[SY * SXP + SXP + 1];

            // x-lerp in packed half2 (both channels at once)
            const __half2 fx2 = __float2half2_rn(fx);
            const __half2 r00 = __hfma2(fx2, __hsub2(c001, c000), c000);
            const __half2 r01 = __hfma2(fx2, __hsub2(c011, c010), c010);
            const __half2 r10 = __hfma2(fx2, __hsub2(c101, c100), c100);
            const __half2 r11 = __hfma2(fx2, __hsub2(c111, c110), c110);

            // y/z combine in fp32
            const float2 f00 = __half22float2(r00);
            const float2 f01 = __half22float2(r01);
            const float2 f10 = __half22float2(r10);
            const float2 f11 = __half22float2(r11);
            a0 = w00 * f00.x + w01 * f01.x + w10 * f10.x + w11 * f11.x;
            a1 = w00 * f00.y + w01 * f01.y + w10 * f10.y + w11 * f11.y;
        } else {
            // rare fallback: sample escapes tile (|flow| > R) — exact fp32
            a0 = 0.0f; a1 = 0.0f;
            const float gzf = 1.0f - fz, gyf = 1.0f - fy, gxf = 1.0f - fx;
            #pragma unroll
            for (int dz = 0; dz < 2; ++dz) {
                const int zi = z0 + dz;
                if ((unsigned)zi >= (unsigned)D) continue;
                const float wz = dz ? fz : gzf;
                #pragma unroll
                for (int dy = 0; dy < 2; ++dy) {
                    const int yi = y0 + dy;
                    if ((unsigned)yi >= (unsigned)H) continue;
                    const float wzy = wz * (dy ? fy : gyf);
                    #pragma unroll
                    for (int dx = 0; dx < 2; ++dx) {
                        const int xi = x0 + dx;
                        if ((unsigned)xi >= (unsigned)W) continue;
                        const float wgt = wzy * (dx ? fx : gxf);
                        const int lin = (zi * H + yi) * W + xi;
                        a0 += wgt * __ldg(s0 + lin);
                        a1 += wgt * __ldg(s1 + lin);
                    }
                }
            }
        }

        __stcs(ob + s,     a0);
        __stcs(ob + s + N, a1);
    }
}

extern "C" void kernel_launch(void* const* d_in, const int* in_sizes, int n_in,
                              void* d_out, int out_size)
{
    const float* src  = (const float*)d_in[0];
    const float* flow = (const float*)d_in[1];
    float* out = (float*)d_out;

    static bool attr_done = false;
    if (!attr_done) {
        cudaFuncSetAttribute(st_v15_kernel,
                             cudaFuncAttributeMaxDynamicSharedMemorySize,
                             SMEM_BYTES);
        attr_done = true;
    }

    dim3 block(TX, TY, 2);                  // 1024 threads
    dim3 grid(W / TX, H / TY, B * NZT);     // 5, 12, 20
    st_v15_kernel<<<grid, block, SMEM_BYTES>>>(src, flow, out);
}